// round 9
// baseline (speedup 1.0000x reference)
#include <cuda_runtime.h>
#include <cstdint>

// DETR-style postprocess:
//   logits [256,1000,80] f32, boxes [256,1000,4] f32 (cxcywh)
//   -> labels [256,300], boxes_xyxy [256,300,4], scores [256,300]
// Output concatenated flat f32: labels | boxes | scores. (verified R3)

#define BATCH      256
#define QQ         1000
#define CC         80
#define NELEM      80000      // QQ*CC per batch
#define NV4        20000      // NELEM/4 (float4 units)
#define KTOP       300
#define CAP        4096
#define NBINS      2048
#define NTHREADS   1024
#define T_STATIC   2.5f

// async streaming pipeline
#define TILE_F4    1024                   // float4 per tile (16 KB)
#define NTILES     20                     // 19 full + tail
#define TAIL_N     544                    // float4 in tile 19 (20000 - 19*1024)
#define STAGES     4
#define DEPTH      3                      // outstanding tiles while processing

#define LBL_OFF    0
#define BOX_OFF    (BATCH * KTOP)            // 76800
#define SCR_OFF    (BATCH * KTOP * 5)        // 384000

// dynamic smem layout (bytes)
#define SM_TILES   0
#define SM_PACK    (STAGES * TILE_F4 * 16)               // 65536
#define SM_HIST    (SM_PACK + CAP * 8)                   // 98304
#define SM_TOTAL   (SM_HIST + NBINS * 4)                 // 106496

// Monotone float->uint key (ascending order preserved)
__device__ __forceinline__ unsigned f2key(float x) {
    unsigned b = __float_as_uint(x);
    return (b & 0x80000000u) ? ~b : (b | 0x80000000u);
}
__device__ __forceinline__ float key2f(unsigned k) {
    unsigned b = (k & 0x80000000u) ? (k & 0x7FFFFFFFu) : ~k;
    return __uint_as_float(b);
}

__device__ __forceinline__ void cp16(void* sdst, const void* gsrc) {
    uint32_t s = (uint32_t)__cvta_generic_to_shared(sdst);
    asm volatile("cp.async.cg.shared.global [%0], [%1], 16;"
                 :: "r"(s), "l"(gsrc) : "memory");
}
__device__ __forceinline__ void cp_commit() {
    asm volatile("cp.async.commit_group;" ::: "memory");
}
template <int N>
__device__ __forceinline__ void cp_wait() {
    asm volatile("cp.async.wait_group %0;" :: "n"(N) : "memory");
}

__global__ __launch_bounds__(NTHREADS, 2)
void postproc_topk_kernel(const float* __restrict__ logits,
                          const float* __restrict__ boxes,
                          float* __restrict__ out)
{
    extern __shared__ __align__(16) char dsmem[];
    float4*             s_tiles = (float4*)(dsmem + SM_TILES);
    unsigned long long* s_pack  = (unsigned long long*)(dsmem + SM_PACK);
    unsigned*           s_hist  = (unsigned*)(dsmem + SM_HIST);
    __shared__ int s_cnt;
    __shared__ int s_b1, s_gt, s_b2;

    const int b   = blockIdx.x;
    const int tid = threadIdx.x;
    const float4* lg4 = (const float4*)(logits + (size_t)b * NELEM);

    if (tid == 0) s_cnt = 0;
    __syncthreads();

    // ---------- Primary path: cp.async staged stream, static threshold ----------
    // prologue: tiles 0..DEPTH-1 (all full tiles)
    #pragma unroll
    for (int t = 0; t < DEPTH; t++) {
        cp16(&s_tiles[t * TILE_F4 + tid], &lg4[t * TILE_F4 + tid]);
        cp_commit();
    }

    #pragma unroll 1
    for (int t = 0; t < NTILES; t++) {
        // issue tile t+DEPTH into its stage (processed >=1 iter ago)
        int tn = t + DEPTH;
        if (tn < NTILES) {
            if (tn < NTILES - 1 || tid < TAIL_N)
                cp16(&s_tiles[(tn & (STAGES - 1)) * TILE_F4 + tid],
                     &lg4[tn * TILE_F4 + tid]);
        }
        cp_commit();                // uniform group count (may be empty)
        cp_wait<DEPTH>();           // this thread's tile t copy is complete

        bool valid = (t < NTILES - 1) || (tid < TAIL_N);
        if (valid) {
            float4 v = s_tiles[(t & (STAGES - 1)) * TILE_F4 + tid];
            float vv[4] = {v.x, v.y, v.z, v.w};
            #pragma unroll
            for (int j = 0; j < 4; j++) {
                if (vv[j] > T_STATIC) {
                    int pos = atomicAdd(&s_cnt, 1);
                    if (pos < CAP) {
                        unsigned idx = (unsigned)((t * TILE_F4 + tid) * 4 + j);
                        s_pack[pos] = ((unsigned long long)f2key(vv[j]) << 32)
                                      | (unsigned long long)(~idx);
                    }
                }
            }
        }
    }
    cp_wait<0>();
    __syncthreads();
    int M = s_cnt;

    // ---------- Fallback: exact 2-level radix select (statistically never) ----------
    if (M < KTOP || M > CAP) {
        for (int i = tid; i < NBINS; i += NTHREADS) s_hist[i] = 0;
        __syncthreads();
        for (int i = tid; i < NV4; i += NTHREADS) {
            float4 v = lg4[i];
            float vv[4] = {v.x, v.y, v.z, v.w};
            #pragma unroll
            for (int j = 0; j < 4; j++)
                atomicAdd(&s_hist[f2key(vv[j]) >> 21], 1u);
        }
        __syncthreads();
        if (tid == 0) {
            int acc = 0, b1 = 0;
            for (int bin = NBINS - 1; bin >= 0; bin--) {
                int c = (int)s_hist[bin];
                if (acc + c >= KTOP) { b1 = bin; break; }
                acc += c;
            }
            s_b1 = b1; s_gt = acc;
        }
        __syncthreads();
        const int b1 = s_b1;
        const int cnt_ge = s_gt + (int)s_hist[b1];

        if (cnt_ge <= CAP) {
            if (tid == 0) s_cnt = 0;
            __syncthreads();
            for (int i = tid; i < NV4; i += NTHREADS) {
                float4 v = lg4[i];
                float vv[4] = {v.x, v.y, v.z, v.w};
                #pragma unroll
                for (int j = 0; j < 4; j++) {
                    unsigned key = f2key(vv[j]);
                    if ((int)(key >> 21) >= b1) {
                        int pos = atomicAdd(&s_cnt, 1);
                        unsigned idx = (unsigned)(i * 4 + j);
                        s_pack[pos] = ((unsigned long long)key << 32)
                                      | (unsigned long long)(~idx);
                    }
                }
            }
            __syncthreads();
            M = s_cnt;
        } else {
            for (int i = tid; i < NBINS; i += NTHREADS) s_hist[i] = 0;
            __syncthreads();
            for (int i = tid; i < NV4; i += NTHREADS) {
                float4 v = lg4[i];
                float vv[4] = {v.x, v.y, v.z, v.w};
                #pragma unroll
                for (int j = 0; j < 4; j++) {
                    unsigned key = f2key(vv[j]);
                    if ((int)(key >> 21) == b1)
                        atomicAdd(&s_hist[(key >> 10) & 0x7FFu], 1u);
                }
            }
            __syncthreads();
            if (tid == 0) {
                int need = KTOP - s_gt;
                int acc = 0, b2 = 0;
                for (int bin = NBINS - 1; bin >= 0; bin--) {
                    int c = (int)s_hist[bin];
                    if (acc + c >= need) { b2 = bin; break; }
                    acc += c;
                }
                s_b2 = b2; s_cnt = 0;
            }
            __syncthreads();
            const int b2 = s_b2;
            for (int i = tid; i < NV4; i += NTHREADS) {
                float4 v = lg4[i];
                float vv[4] = {v.x, v.y, v.z, v.w};
                #pragma unroll
                for (int j = 0; j < 4; j++) {
                    unsigned key = f2key(vv[j]);
                    int hb = (int)(key >> 21);
                    bool take = (hb > b1) ||
                                (hb == b1 && (int)((key >> 10) & 0x7FFu) >= b2);
                    if (take) {
                        int pos = atomicAdd(&s_cnt, 1);
                        if (pos < CAP) {
                            unsigned idx = (unsigned)(i * 4 + j);
                            s_pack[pos] = ((unsigned long long)key << 32)
                                          | (unsigned long long)(~idx);
                        }
                    }
                }
            }
            __syncthreads();
            M = min(s_cnt, CAP);
        }
    }

    // pad one zero pack so the paired inner loop can read an even count
    if (tid == 0 && M < CAP) s_pack[M] = 0ULL;
    __syncthreads();
    const int Mpair = (M + 1) >> 1;
    const ulonglong2* sp2 = (const ulonglong2*)s_pack;

    // ---------- Exact ranking (descending key, lower idx first on ties) ----------
    for (int i = tid; i < M; i += NTHREADS) {
        unsigned long long pi = s_pack[i];
        int r = 0;
        for (int j = 0; j < Mpair; j++) {
            ulonglong2 pj = sp2[j];
            r += (pj.x > pi) + (pj.y > pi);
        }
        if (r < KTOP) {
            unsigned key = (unsigned)(pi >> 32);
            unsigned idx = ~(unsigned)(pi & 0xFFFFFFFFull);
            int q = (int)(idx / CC);
            int c = (int)(idx % CC);
            float lv = key2f(key);
            float score = 1.0f / (1.0f + expf(-lv));

            size_t slot = (size_t)b * KTOP + r;
            out[LBL_OFF + slot] = (float)c;
            out[SCR_OFF + slot] = score;

            float4 bx = ((const float4*)boxes)[(size_t)b * QQ + q];
            float4 o;
            o.x = bx.x - 0.5f * bx.z;
            o.y = bx.y - 0.5f * bx.w;
            o.z = bx.x + 0.5f * bx.z;
            o.w = bx.y + 0.5f * bx.w;
            ((float4*)(out + BOX_OFF))[slot] = o;
        }
    }
}

extern "C" void kernel_launch(void* const* d_in, const int* in_sizes, int n_in,
                              void* d_out, int out_size)
{
    const float* logits = (const float*)d_in[0];
    const float* boxes  = (const float*)d_in[1];
    float* out = (float*)d_out;

    cudaFuncSetAttribute(postproc_topk_kernel,
                         cudaFuncAttributeMaxDynamicSharedMemorySize, SM_TOTAL);
    postproc_topk_kernel<<<BATCH, NTHREADS, SM_TOTAL>>>(logits, boxes, out);
}